// round 7
// baseline (speedup 1.0000x reference)
#include <cuda_runtime.h>
#include <math.h>

#define NB 8
#define NC 12
#define NNtok 785
#define NS 784
#define NH 28
#define ND 768
#define KHID 512
#define PNUM 84
#define SCL 0.7f
#define TPB 1024
#define NWB 32
#define NWA 25                     // warps covering s<784
#define NC4TOT (NB * NS * (ND / 4))   // 1,204,224 float4 (rows 1..784)
#define NCPB 140                   // copy blocks -> grid = 8 + 140 = 148 = 1 wave
#define CSTRIDE (NCPB * TPB)

__device__ int g_patch[NB * NS];   // patch index by rank (first seln used)

__device__ __forceinline__ unsigned f2key(float v) {
    unsigned b = __float_as_uint(v);
    return (b & 0x80000000u) ? ~b : (b | 0x80000000u);   // order-preserving
}

__global__ __launch_bounds__(TPB) void kMain(
    const float* __restrict__ x,  const float* __restrict__ w1,
    const float* __restrict__ w2, const float* __restrict__ hs,
    float* __restrict__ out, int seln)
{
    __shared__ unsigned      msel[NC][25];      // selection bitmasks
    __shared__ int           hist[NC][256];     // per-channel radix hist
    __shared__ unsigned char whist[NWA][256];   // per-warp conv-value hist
    __shared__ int           c0[NS];
    __shared__ float         msh[NS];
    __shared__ int           sfx[256];
    __shared__ float         up[KHID], um[KHID];
    __shared__ float redf[NWB], redf2[NWB], redf3[NWB], redf4[NWB];
    __shared__ int   redi[NWB];
    __shared__ float s_mean, s_w0, s_w1, s_pa, s_cp, s_cm;
    __shared__ int   s_anchor;

    const int tid = threadIdx.x, lane = tid & 31, warp = tid >> 5;

    if (blockIdx.x >= NB) {
        // ================= copy blocks: hs rows 1..784 -> out ==============
        const float4* hin = (const float4*)hs;
        float4* o4 = (float4*)out;
        const int cb = blockIdx.x - NB;
        float4 v[9]; int idx[9]; bool ok[9];
        #pragma unroll
        for (int j = 0; j < 9; j++) {
            int k = cb * TPB + tid + j * CSTRIDE;
            ok[j] = (k < NC4TOT);
            if (ok[j]) {
                int b  = k / (NS * (ND / 4));
                int r  = k - b * (NS * (ND / 4));
                int n  = r / (ND / 4);
                int d4 = r - n * (ND / 4);
                idx[j] = (b * NNtok + n + 1) * (ND / 4) + d4;
                v[j]   = hin[idx[j]];
            }
        }
        #pragma unroll
        for (int j = 0; j < 9; j++) if (ok[j]) o4[idx[j]] = v[j];
        return;
    }

    // ==================== compute block for batch b ========================
    const int b = blockIdx.x;

    for (int i = tid; i < NWA * 256 / 4; i += TPB) ((int*)whist)[i] = 0;

    // ---- warp-local top-84 radix select, one channel per warp (0..11) ----
    if (warp < NC) {
        const int c = warp;
        const float* row = x + ((long long)(b * NC + c)) * NNtok * NNtok + 1;
        unsigned pref = 0u; int rem = PNUM;
        #pragma unroll
        for (int pass = 0; pass < 4; pass++) {
            const int shift = 24 - 8 * pass;
            const unsigned mhi = (pass == 0) ? 0u : (0xFFFFFFFFu << (shift + 8));
            #pragma unroll
            for (int i = 0; i < 8; i++) hist[c][lane * 8 + i] = 0;
            __syncwarp();
            #pragma unroll
            for (int j = 0; j < 25; j++) {
                int s = lane + 32 * j;
                if (s < NS) {
                    unsigned u = f2key(row[s]);     // L1-hot after pass 0
                    if ((u & mhi) == pref)
                        atomicAdd(&hist[c][(u >> shift) & 255u], 1);
                }
            }
            __syncwarp();
            int h[8], S = 0;
            #pragma unroll
            for (int i = 0; i < 8; i++) { h[i] = hist[c][lane * 8 + i]; S += h[i]; }
            int s = S;                               // inclusive suffix over lanes
            #pragma unroll
            for (int o = 1; o < 32; o <<= 1) {
                int n = __shfl_down_sync(0xFFFFFFFFu, s, o);
                if (lane + o < 32) s += n;
            }
            int run = s - S;                         // sum over lanes > me
            int fbin = -1, fgt = 0;
            #pragma unroll
            for (int i = 7; i >= 0; i--) {           // bins high->low within lane
                int gt = run;                        // # keys strictly greater
                if (gt < rem && gt + h[i] >= rem) { fbin = lane * 8 + i; fgt = gt; }
                run += h[i];
            }
            unsigned fm = __ballot_sync(0xFFFFFFFFu, fbin >= 0);
            int src = __ffs(fm) - 1;
            int bin = __shfl_sync(0xFFFFFFFFu, fbin, src);
            int gt  = __shfl_sync(0xFFFFFFFFu, fgt,  src);
            pref |= ((unsigned)bin) << shift;
            rem  -= gt;
            __syncwarp();
        }
        const unsigned T = pref; const int need = rem;  // ties: ascending index
        int cum = 0;
        #pragma unroll
        for (int j = 0; j < 25; j++) {
            int s = lane + 32 * j;
            bool valid = (s < NS);
            unsigned u = valid ? f2key(row[s]) : (T ^ 1u);
            unsigned eqm = __ballot_sync(0xFFFFFFFFu, valid && (u == T));
            bool sel = valid && (u > T ||
                      (u == T && (cum + __popc(eqm & ((1u << lane) - 1u)) < need)));
            unsigned smask = __ballot_sync(0xFFFFFFFFu, sel);
            if (lane == 0) msel[c][j] = smask;
            cum += __popc(eqm);
        }
    }
    __syncthreads();

    // ---- m[s] = sum_c (sel ? v : 0.7v);  c0[s] = sum_c sel ----------------
    const bool act = (tid < NS);
    float m = 0.f;
    if (act) {
        const long long xb = (long long)b * NC * NNtok * NNtok;
        const int jw = tid >> 5; const unsigned bit = 1u << (tid & 31);
        int cnt = 0;
        #pragma unroll
        for (int c = 0; c < NC; c++) {
            float v = x[xb + (long long)c * NNtok * NNtok + 1 + tid];  // L1-hot
            bool sel = (msel[c][jw] & bit) != 0u;
            m += sel ? v : v * SCL;
            cnt += sel ? 1 : 0;
        }
        msh[tid] = m;
        c0[tid]  = cnt;
    }
    float ps = act ? m : 0.f;
    for (int o = 16; o; o >>= 1) ps += __shfl_xor_sync(0xFFFFFFFFu, ps, o);
    if (lane == 0) redf[warp] = ps;
    __syncthreads();
    if (tid == 0) {
        float t = 0.f;
        for (int w = 0; w < NWB; w++) t += redf[w];
        s_mean = t / (float)NS;
    }
    __syncthreads();

    // ---- anchor = argmax(binary*m/C), first-index tie-break --------------
    float bv = -1e30f; int bi = NS;
    if (act) { float v = (m > s_mean) ? m * (1.0f / NC) : 0.0f; bv = v; bi = tid; }
    for (int o = 16; o; o >>= 1) {
        float ov = __shfl_xor_sync(0xFFFFFFFFu, bv, o);
        int   oi = __shfl_xor_sync(0xFFFFFFFFu, bi, o);
        if (ov > bv || (ov == bv && oi < bi)) { bv = ov; bi = oi; }
    }
    if (lane == 0) { redf[warp] = bv; redi[warp] = bi; }
    __syncthreads();
    if (tid == 0) {
        float v = redf[0]; int i = redi[0];
        for (int w = 1; w < NWB; w++)
            if (redf[w] > v || (redf[w] == v && redi[w] < i)) { v = redf[w]; i = redi[w]; }
        s_anchor = i;
    }
    __syncthreads();
    const int anchor = s_anchor;
    const float ai = (float)(anchor / NH), aj = (float)(anchor % NH);

    // ---- w0 = sum pw*dist, w1 = sum pw*ang, c+- = sum pw^2 by sign -------
    float w0 = 0.f, w1s = 0.f, cpv = 0.f, cmv = 0.f;
    if (act) {
        float p   = m * (1.0f / NC);
        float rc0 = ((float)(tid / NH) - ai) / (float)NH;
        float rc1 = ((float)(tid % NH) - aj) / (float)NH;
        w0  = p * sqrtf(rc0 * rc0 + rc1 * rc1);
        w1s = p * (atan2f(rc1, rc0) * 0.3183098861837907f + 1.0f) * 0.5f;
        if (p > 0.f) cpv = p * p; else if (p < 0.f) cmv = p * p;
    }
    for (int o = 16; o; o >>= 1) {
        w0  += __shfl_xor_sync(0xFFFFFFFFu, w0,  o);
        w1s += __shfl_xor_sync(0xFFFFFFFFu, w1s, o);
        cpv += __shfl_xor_sync(0xFFFFFFFFu, cpv, o);
        cmv += __shfl_xor_sync(0xFFFFFFFFu, cmv, o);
    }
    if (lane == 0) { redf[warp] = w0; redf2[warp] = w1s; redf3[warp] = cpv; redf4[warp] = cmv; }
    __syncthreads();
    if (tid == 0) {
        float a = 0, bb = 0, c = 0, d = 0;
        for (int w = 0; w < NWB; w++) { a += redf[w]; bb += redf2[w]; c += redf3[w]; d += redf4[w]; }
        s_w0 = a; s_w1 = bb;
        s_pa = msh[anchor] * (1.0f / NC);
        s_cp = c; s_cm = d;
    }
    __syncthreads();

    // ---- u1 halves; 3x3 conv + per-warp value histogram ------------------
    if (tid < KHID) {
        float u = s_w0 * w1[tid] + s_w1 * w1[KHID + tid];
        up[tid] = fmaxf(u, 0.f);
        um[tid] = fmaxf(-u, 0.f);
    }
    int vcc = 0; unsigned mm;
    if (act) {
        int i0 = tid / NH, j0 = tid % NH;
        #pragma unroll
        for (int di = -1; di <= 1; di++)
            #pragma unroll
            for (int dj = -1; dj <= 1; dj++) {
                int ii = i0 + di, jj = j0 + dj;
                if (ii >= 0 && ii < NH && jj >= 0 && jj < NH)
                    vcc += (2 - abs(di)) * (2 - abs(dj)) * c0[ii * NH + jj];
            }
    }
    {
        int key = act ? vcc : 999;
        mm = __match_any_sync(0xFFFFFFFFu, key);
        if (act && lane == (__ffs(mm) - 1))
            whist[warp][vcc] = (unsigned char)__popc(mm);   // single writer
    }
    __syncthreads();

    // ---- sfx[v] = # strictly greater (suffix over 256 bins) --------------
    if (tid < 256) {
        int h = 0;
        #pragma unroll
        for (int r = 0; r < NWA; r++) h += (int)whist[r][tid];
        int s = h;
        #pragma unroll
        for (int o = 1; o < 32; o <<= 1) {
            int n = __shfl_up_sync(0xFFFFFFFFu, s, o);
            if (lane >= o) s += n;
        }
        if (lane == 31) redi[tid >> 5] = s;
        __syncthreads();
        int off = 0, total = 0;
        #pragma unroll
        for (int r = 0; r < 8; r++) {
            int w = redi[r]; total += w; if (r < (tid >> 5)) off += w;
        }
        sfx[tid] = total - (s + off);
    } else {
        __syncthreads();
    }
    __syncthreads();

    // ---- stable descending ranks -> g_patch ------------------------------
    if (act) {
        int g = sfx[vcc];
        if (g < seln) {
            int e = __popc(mm & ((1u << lane) - 1u));
            for (int r = 0; r < warp; r++) e += (int)whist[r][vcc];
            int rk = g + e;
            if (rk < seln) g_patch[b * NS + rk] = tid + 1;
        }
    }

    // ---- struct GEMV + write output row 0 --------------------------------
    if (tid < ND) {
        float ap = 0.f, am = 0.f;
        const float* wp = w2 + tid;
        #pragma unroll 4
        for (int k = 0; k < KHID; k++) {
            float w = wp[k * ND];
            ap += up[k] * w;
            am += um[k] * w;
        }
        float val = s_pa * (s_cp * ap - s_cm * am);
        val = val > 0.f ? val : 0.2f * val;
        const int fi = b * NNtok * ND + tid;
        out[fi] = hs[fi] + val;
    }
}

// ================= Kernel 2: selected = hs[b, patch_idx] ===================
__global__ __launch_bounds__(256) void kGather(const float4* __restrict__ hin,
                                               float4* __restrict__ o4,
                                               int seln, int ngat4)
{
    const int base = blockIdx.x * 1024 + threadIdx.x;
    #pragma unroll
    for (int j = 0; j < 4; j++) {
        int k = base + j * 256;
        if (k < ngat4) {
            int row = k / (ND / 4), d4 = k - row * (ND / 4);
            int b = row / seln, q = row - b * seln;
            int p = g_patch[b * NS + q];       // in [1,784]: unmodified hs rows
            o4[NB * NNtok * (ND / 4) + k] = hin[(b * NNtok + p) * (ND / 4) + d4];
        }
    }
}

// ---------------- launch ----------------
extern "C" void kernel_launch(void* const* d_in, const int* in_sizes, int n_in,
                              void* d_out, int out_size)
{
    const float* hs = (const float*)d_in[0];
    const float* x  = (const float*)d_in[1];
    const float* w1 = (const float*)d_in[2];
    const float* w2 = (const float*)d_in[3];

    const int hs_elems = NB * NNtok * ND;
    int seln = (out_size - hs_elems) / (NB * ND);
    if (seln < 1) seln = 1;

    kMain<<<NB + NCPB, TPB>>>(x, w1, w2, hs, (float*)d_out, seln);
    int ngat4 = NB * seln * (ND / 4);
    kGather<<<(ngat4 + 1023) / 1024, 256>>>((const float4*)hs, (float4*)d_out,
                                            seln, ngat4);
}

// round 8
// speedup vs baseline: 1.6423x; 1.6423x over previous
#include <cuda_runtime.h>
#include <math.h>

#define NB 8
#define NC 12
#define NNtok 785
#define NS 784
#define NH 28
#define ND 768
#define KHID 512
#define PNUM 84
#define SCL 0.7f
#define TPB 1024
#define NWB 32
#define NWA 25                        // warps covering s<784
#define NSUB 2                        // compute sub-blocks per batch
#define NCB (NB * NSUB)               // 16 compute blocks
#define JPB (ND / NSUB)               // 384 columns per compute block
#define NC4TOT (NB * NS * (ND / 4))   // 1,204,224 float4 (rows 1..784)
#define NCPB (148 - NCB)              // 132 copy blocks -> grid 148 = 1 wave
#define CSTRIDE (NCPB * TPB)

__device__ __forceinline__ unsigned f2key(float v) {
    unsigned b = __float_as_uint(v);
    return (b & 0x80000000u) ? ~b : (b | 0x80000000u);   // order-preserving
}

__global__ __launch_bounds__(TPB) void kAll(
    const float* __restrict__ x,  const float* __restrict__ w1,
    const float* __restrict__ w2, const float* __restrict__ hs,
    float* __restrict__ out, int seln)
{
    const int tid = threadIdx.x, lane = tid & 31, warp = tid >> 5;

    if (blockIdx.x >= NCB) {
        // ================= copy blocks: hs rows 1..784 -> out ==============
        const float4* hin = (const float4*)hs;
        float4* o4 = (float4*)out;
        const int cb = blockIdx.x - NCB;
        float4 v[9]; int idx[9]; bool ok[9];
        #pragma unroll
        for (int j = 0; j < 9; j++) {
            int k = cb * TPB + tid + j * CSTRIDE;
            ok[j] = (k < NC4TOT);
            if (ok[j]) {
                int b  = k / (NS * (ND / 4));
                int r  = k - b * (NS * (ND / 4));
                int n  = r / (ND / 4);
                int d4 = r - n * (ND / 4);
                idx[j] = (b * NNtok + n + 1) * (ND / 4) + d4;
                v[j]   = hin[idx[j]];
            }
        }
        #pragma unroll
        for (int j = 0; j < 9; j++) if (ok[j]) o4[idx[j]] = v[j];
        return;
    }

    // ============== compute block (b, sub): redundant per-batch stats ======
    __shared__ unsigned      msel[NC][25];      // selection bitmasks
    __shared__ int           hist[NC][256];     // per-channel radix hist
    __shared__ unsigned char whist[NWA][256];   // per-warp conv-value hist
    __shared__ int           c0[NS];
    __shared__ float         msh[NS];
    __shared__ int           sfx[256];
    __shared__ int           spatch[NS];        // patch idx by rank
    __shared__ float         scoef[KHID];       // cp*u+ - cm*u-
    __shared__ float         gpart[NSUB * JPB]; // GEMV k-chunk partials
    __shared__ float redf[NWB], redf2[NWB], redf3[NWB], redf4[NWB];
    __shared__ int   redi[NWB];
    __shared__ float s_mean, s_w0, s_w1, s_pa, s_cp, s_cm;
    __shared__ int   s_anchor;

    const int b = blockIdx.x >> 1, sub = blockIdx.x & 1;

    for (int i = tid; i < NWA * 256 / 4; i += TPB) ((int*)whist)[i] = 0;

    // ---- warp-local top-84 radix select, one channel per warp (0..11) ----
    if (warp < NC) {
        const int c = warp;
        const float* row = x + ((long long)(b * NC + c)) * NNtok * NNtok + 1;
        unsigned pref = 0u; int rem = PNUM;
        #pragma unroll
        for (int pass = 0; pass < 4; pass++) {
            const int shift = 24 - 8 * pass;
            const unsigned mhi = (pass == 0) ? 0u : (0xFFFFFFFFu << (shift + 8));
            #pragma unroll
            for (int i = 0; i < 8; i++) hist[c][lane * 8 + i] = 0;
            __syncwarp();
            #pragma unroll
            for (int j = 0; j < 25; j++) {
                int s = lane + 32 * j;
                if (s < NS) {
                    unsigned u = f2key(row[s]);       // L1-hot after pass 0
                    if ((u & mhi) == pref)
                        atomicAdd(&hist[c][(u >> shift) & 255u], 1);
                }
            }
            __syncwarp();
            int h[8], S = 0;
            #pragma unroll
            for (int i = 0; i < 8; i++) { h[i] = hist[c][lane * 8 + i]; S += h[i]; }
            int s = S;                                 // suffix over lanes
            #pragma unroll
            for (int o = 1; o < 32; o <<= 1) {
                int n = __shfl_down_sync(0xFFFFFFFFu, s, o);
                if (lane + o < 32) s += n;
            }
            int run = s - S;                           // sum over lanes > me
            int fbin = -1, fgt = 0;
            #pragma unroll
            for (int i = 7; i >= 0; i--) {
                int gt = run;                          // # keys strictly greater
                if (gt < rem && gt + h[i] >= rem) { fbin = lane * 8 + i; fgt = gt; }
                run += h[i];
            }
            unsigned fm = __ballot_sync(0xFFFFFFFFu, fbin >= 0);
            int src = __ffs(fm) - 1;
            int bin = __shfl_sync(0xFFFFFFFFu, fbin, src);
            int gt  = __shfl_sync(0xFFFFFFFFu, fgt,  src);
            pref |= ((unsigned)bin) << shift;
            rem  -= gt;
            __syncwarp();
        }
        const unsigned T = pref; const int need = rem;  // ties ascending-index
        int cum = 0;
        #pragma unroll
        for (int j = 0; j < 25; j++) {
            int s = lane + 32 * j;
            bool valid = (s < NS);
            unsigned u = valid ? f2key(row[s]) : (T ^ 1u);
            unsigned eqm = __ballot_sync(0xFFFFFFFFu, valid && (u == T));
            bool sel = valid && (u > T ||
                      (u == T && (cum + __popc(eqm & ((1u << lane) - 1u)) < need)));
            unsigned smask = __ballot_sync(0xFFFFFFFFu, sel);
            if (lane == 0) msel[c][j] = smask;
            cum += __popc(eqm);
        }
    }
    __syncthreads();

    // ---- m[s] = sum_c (sel ? v : 0.7v);  c0[s] = sum_c sel ---------------
    const bool act = (tid < NS);
    float m = 0.f;
    if (act) {
        const long long xb = (long long)b * NC * NNtok * NNtok;
        const int jw = tid >> 5; const unsigned bit = 1u << (tid & 31);
        int cnt = 0;
        #pragma unroll
        for (int c = 0; c < NC; c++) {
            float v = x[xb + (long long)c * NNtok * NNtok + 1 + tid];  // L1-hot
            bool sel = (msel[c][jw] & bit) != 0u;
            m += sel ? v : v * SCL;
            cnt += sel ? 1 : 0;
        }
        msh[tid] = m;
        c0[tid]  = cnt;
    }
    float ps = act ? m : 0.f;
    for (int o = 16; o; o >>= 1) ps += __shfl_xor_sync(0xFFFFFFFFu, ps, o);
    if (lane == 0) redf[warp] = ps;
    __syncthreads();
    if (tid == 0) {
        float t = 0.f;
        for (int w = 0; w < NWB; w++) t += redf[w];
        s_mean = t / (float)NS;
    }
    __syncthreads();

    // ---- anchor = argmax(binary*m/C), first-index tie-break --------------
    float bv = -1e30f; int bi = NS;
    if (act) { float v = (m > s_mean) ? m * (1.0f / NC) : 0.0f; bv = v; bi = tid; }
    for (int o = 16; o; o >>= 1) {
        float ov = __shfl_xor_sync(0xFFFFFFFFu, bv, o);
        int   oi = __shfl_xor_sync(0xFFFFFFFFu, bi, o);
        if (ov > bv || (ov == bv && oi < bi)) { bv = ov; bi = oi; }
    }
    if (lane == 0) { redf[warp] = bv; redi[warp] = bi; }
    __syncthreads();
    if (tid == 0) {
        float v = redf[0]; int i = redi[0];
        for (int w = 1; w < NWB; w++)
            if (redf[w] > v || (redf[w] == v && redi[w] < i)) { v = redf[w]; i = redi[w]; }
        s_anchor = i;
    }
    __syncthreads();
    const int anchor = s_anchor;
    const float ai = (float)(anchor / NH), aj = (float)(anchor % NH);

    // ---- w0 = sum pw*dist, w1 = sum pw*ang, c+- = sum pw^2 by sign -------
    float w0 = 0.f, w1s = 0.f, cpv = 0.f, cmv = 0.f;
    if (act) {
        float p   = m * (1.0f / NC);
        float rc0 = ((float)(tid / NH) - ai) / (float)NH;
        float rc1 = ((float)(tid % NH) - aj) / (float)NH;
        w0  = p * sqrtf(rc0 * rc0 + rc1 * rc1);
        w1s = p * (atan2f(rc1, rc0) * 0.3183098861837907f + 1.0f) * 0.5f;
        if (p > 0.f) cpv = p * p; else if (p < 0.f) cmv = p * p;
    }
    for (int o = 16; o; o >>= 1) {
        w0  += __shfl_xor_sync(0xFFFFFFFFu, w0,  o);
        w1s += __shfl_xor_sync(0xFFFFFFFFu, w1s, o);
        cpv += __shfl_xor_sync(0xFFFFFFFFu, cpv, o);
        cmv += __shfl_xor_sync(0xFFFFFFFFu, cmv, o);
    }
    if (lane == 0) { redf[warp] = w0; redf2[warp] = w1s; redf3[warp] = cpv; redf4[warp] = cmv; }
    __syncthreads();
    if (tid == 0) {
        float a = 0, bb = 0, c = 0, d = 0;
        for (int w = 0; w < NWB; w++) { a += redf[w]; bb += redf2[w]; c += redf3[w]; d += redf4[w]; }
        s_w0 = a; s_w1 = bb;
        s_pa = msh[anchor] * (1.0f / NC);
        s_cp = c; s_cm = d;
    }
    __syncthreads();

    // ---- coef[k] = u>0 ? cp*u : cm*u  (since cp*u+ - cm*u- collapses) ----
    if (tid < KHID) {
        float u = s_w0 * w1[tid] + s_w1 * w1[KHID + tid];
        scoef[tid] = u * (u > 0.f ? s_cp : s_cm);
    }

    // ---- 3x3 conv + per-warp value histogram -----------------------------
    int vcc = 0; unsigned mm;
    if (act) {
        int i0 = tid / NH, j0 = tid % NH;
        #pragma unroll
        for (int di = -1; di <= 1; di++)
            #pragma unroll
            for (int dj = -1; dj <= 1; dj++) {
                int ii = i0 + di, jj = j0 + dj;
                if (ii >= 0 && ii < NH && jj >= 0 && jj < NH)
                    vcc += (2 - abs(di)) * (2 - abs(dj)) * c0[ii * NH + jj];
            }
    }
    {
        int key = act ? vcc : 999;
        mm = __match_any_sync(0xFFFFFFFFu, key);
        if (act && lane == (__ffs(mm) - 1))
            whist[warp][vcc] = (unsigned char)__popc(mm);
    }
    __syncthreads();

    // ---- sfx[v] = # strictly greater (suffix over 256 bins) --------------
    if (tid < 256) {
        int h = 0;
        #pragma unroll
        for (int r = 0; r < NWA; r++) h += (int)whist[r][tid];
        int s = h;
        #pragma unroll
        for (int o = 1; o < 32; o <<= 1) {
            int n = __shfl_up_sync(0xFFFFFFFFu, s, o);
            if (lane >= o) s += n;
        }
        if (lane == 31) redi[tid >> 5] = s;
        __syncthreads();
        int off = 0, total = 0;
        #pragma unroll
        for (int r = 0; r < 8; r++) {
            int w = redi[r]; total += w; if (r < (tid >> 5)) off += w;
        }
        sfx[tid] = total - (s + off);
    } else {
        __syncthreads();
    }
    __syncthreads();

    // ---- stable descending ranks -> smem patch list ----------------------
    if (act) {
        int g = sfx[vcc];
        if (g < seln) {
            int e = __popc(mm & ((1u << lane) - 1u));
            for (int r = 0; r < warp; r++) e += (int)whist[r][vcc];
            int rk = g + e;                 // ties by ascending index (stable)
            if (rk < seln) spatch[rk] = tid + 1;
        }
    }

    // ---- GEMV over this block's 384 columns: 2 k-chunks x 384 threads ----
    if (tid < NSUB * JPB) {
        const int jc = tid % JPB, ks = tid / JPB;       // ks in 0..1
        const int j  = sub * JPB + jc;
        const float* wp = w2 + j;
        float acc = 0.f;
        #pragma unroll 8
        for (int k = ks * (KHID / 2); k < (ks + 1) * (KHID / 2); k++)
            acc += scoef[k] * wp[k * ND];
        gpart[tid] = acc;
    }
    __syncthreads();
    if (tid < JPB) {
        float val = s_pa * (gpart[tid] + gpart[JPB + tid]);
        val = val > 0.f ? val : 0.2f * val;
        const int fi = b * NNtok * ND + sub * JPB + tid;   // row 0, our cols
        out[fi] = hs[fi] + val;
    }

    // ---- gather: this sub-block handles rows q = sub, sub+2, ... ---------
    {
        const float4* hin = (const float4*)hs;
        float4* o4 = (float4*)out;
        const int nh = (seln - sub + 1) / 2;               // # rows we own
        const int tot = nh * (ND / 4);
        for (int t = tid; t < tot; t += TPB) {
            int r  = t / (ND / 4);
            int d4 = t - r * (ND / 4);
            int q  = 2 * r + sub;
            int p  = spatch[q];            // in [1,784]: unmodified hs rows
            o4[NB * NNtok * (ND / 4) + (b * seln + q) * (ND / 4) + d4] =
                hin[(b * NNtok + p) * (ND / 4) + d4];
        }
    }
}

// ---------------- launch ----------------
extern "C" void kernel_launch(void* const* d_in, const int* in_sizes, int n_in,
                              void* d_out, int out_size)
{
    const float* hs = (const float*)d_in[0];
    const float* x  = (const float*)d_in[1];
    const float* w1 = (const float*)d_in[2];
    const float* w2 = (const float*)d_in[3];

    const int hs_elems = NB * NNtok * ND;
    int seln = (out_size - hs_elems) / (NB * ND);
    if (seln < 1) seln = 1;

    kAll<<<NCB + NCPB, TPB>>>(x, w1, w2, hs, (float*)d_out, seln);
}

// round 10
// speedup vs baseline: 1.6593x; 1.0104x over previous
#include <cuda_runtime.h>
#include <math.h>

#define NB 8
#define NC 12
#define NNtok 785
#define NS 784
#define NH 28
#define ND 768
#define KHID 512
#define PNUM 84
#define SCL 0.7f
#define TPB 1024
#define NWB 32
#define NWA 25                        // warps covering s<784
#define NSUB 2                        // compute sub-blocks per batch
#define NCB (NB * NSUB)               // 16 compute blocks
#define NC4TOT (NB * NS * (ND / 4))   // 1,204,224 float4 (rows 1..784)
#define NCPB (148 - NCB)              // 132 copy blocks -> grid 148 = 1 wave
#define CSTRIDE (NCPB * TPB)

__device__ __forceinline__ unsigned f2key(float v) {
    unsigned b = __float_as_uint(v);
    return (b & 0x80000000u) ? ~b : (b | 0x80000000u);   // order-preserving
}

__global__ __launch_bounds__(TPB) void kAll(
    const float* __restrict__ x,  const float* __restrict__ w1,
    const float* __restrict__ w2, const float* __restrict__ hs,
    float* __restrict__ out, int seln)
{
    const int tid = threadIdx.x, lane = tid & 31, warp = tid >> 5;

    if (blockIdx.x >= NCB) {
        // ================= copy blocks: hs rows 1..784 -> out ==============
        const float4* hin = (const float4*)hs;
        float4* o4 = (float4*)out;
        const int cb = blockIdx.x - NCB;
        float4 v[9]; int idx[9]; bool ok[9];
        #pragma unroll
        for (int j = 0; j < 9; j++) {
            int k = cb * TPB + tid + j * CSTRIDE;
            ok[j] = (k < NC4TOT);
            if (ok[j]) {
                int b  = k / (NS * (ND / 4));
                int r  = k - b * (NS * (ND / 4));
                int n  = r / (ND / 4);
                int d4 = r - n * (ND / 4);
                idx[j] = (b * NNtok + n + 1) * (ND / 4) + d4;
                v[j]   = __ldcs(hin + idx[j]);
            }
        }
        #pragma unroll
        for (int j = 0; j < 9; j++) if (ok[j]) __stcs(o4 + idx[j], v[j]);
        return;
    }

    // ============== compute block (b, sub): redundant per-batch stats ======
    __shared__ unsigned      msel[NC][25];      // selection bitmasks
    __shared__ int           hist[NC][256];     // per-channel radix hist
    __shared__ unsigned char whist[NWA][256];   // per-warp conv-value hist
    __shared__ unsigned char c0[NS];
    __shared__ float         msh[NS];
    __shared__ int           sfx[256];
    __shared__ short         spatch[NS];        // patch idx by rank
    __shared__ float         scoef[KHID];       // (u>0?cp:cm)*u
    __shared__ float4        gp4[4 * 192];      // GEMV k-chunk partials
    __shared__ float redf[NWB], redf2[NWB], redf3[NWB], redf4[NWB];
    __shared__ int   redi[NWB];
    __shared__ float s_mean, s_w0, s_w1, s_pa, s_cp, s_cm;
    __shared__ int   s_anchor;

    const int b = blockIdx.x >> 1, sub = blockIdx.x & 1;

    for (int i = tid; i < NWA * 256 / 4; i += TPB) ((int*)whist)[i] = 0;

    // ---- warp-local top-84 radix select, one channel per warp (0..11) ----
    if (warp < NC) {
        const int c = warp;
        const float* row = x + ((long long)(b * NC + c)) * NNtok * NNtok + 1;
        unsigned pref = 0u; int rem = PNUM;
        #pragma unroll
        for (int pass = 0; pass < 4; pass++) {
            const int shift = 24 - 8 * pass;
            const unsigned mhi = (pass == 0) ? 0u : (0xFFFFFFFFu << (shift + 8));
            #pragma unroll
            for (int i = 0; i < 8; i++) hist[c][lane * 8 + i] = 0;
            __syncwarp();
            #pragma unroll
            for (int j = 0; j < 25; j++) {
                int s = lane + 32 * j;
                if (s < NS) {
                    unsigned u = f2key(row[s]);       // L1-hot after pass 0
                    if ((u & mhi) == pref)
                        atomicAdd(&hist[c][(u >> shift) & 255u], 1);
                }
            }
            __syncwarp();
            int h[8], S = 0;
            #pragma unroll
            for (int i = 0; i < 8; i++) { h[i] = hist[c][lane * 8 + i]; S += h[i]; }
            int s = S;                                 // suffix over lanes
            #pragma unroll
            for (int o = 1; o < 32; o <<= 1) {
                int n = __shfl_down_sync(0xFFFFFFFFu, s, o);
                if (lane + o < 32) s += n;
            }
            int run = s - S;                           // sum over lanes > me
            int fbin = -1, fgt = 0;
            #pragma unroll
            for (int i = 7; i >= 0; i--) {
                int gt = run;                          // # keys strictly greater
                if (gt < rem && gt + h[i] >= rem) { fbin = lane * 8 + i; fgt = gt; }
                run += h[i];
            }
            unsigned fm = __ballot_sync(0xFFFFFFFFu, fbin >= 0);
            int src = __ffs(fm) - 1;
            int bin = __shfl_sync(0xFFFFFFFFu, fbin, src);
            int gt  = __shfl_sync(0xFFFFFFFFu, fgt,  src);
            pref |= ((unsigned)bin) << shift;
            rem  -= gt;
            __syncwarp();
        }
        const unsigned T = pref; const int need = rem;  // ties ascending-index
        int cum = 0;
        #pragma unroll
        for (int j = 0; j < 25; j++) {
            int s = lane + 32 * j;
            bool valid = (s < NS);
            unsigned u = valid ? f2key(row[s]) : (T ^ 1u);
            unsigned eqm = __ballot_sync(0xFFFFFFFFu, valid && (u == T));
            bool sel = valid && (u > T ||
                      (u == T && (cum + __popc(eqm & ((1u << lane) - 1u)) < need)));
            unsigned smask = __ballot_sync(0xFFFFFFFFu, sel);
            if (lane == 0) msel[c][j] = smask;
            cum += __popc(eqm);
        }
    }
    __syncthreads();

    // ---- m[s] = sum_c (sel ? v : 0.7v);  c0[s] = sum_c sel ---------------
    const bool act = (tid < NS);
    float m = 0.f;
    if (act) {
        const long long xb = (long long)b * NC * NNtok * NNtok;
        const int jw = tid >> 5; const unsigned bit = 1u << (tid & 31);
        int cnt = 0;
        #pragma unroll
        for (int c = 0; c < NC; c++) {
            float v = x[xb + (long long)c * NNtok * NNtok + 1 + tid];  // L1-hot
            bool sel = (msel[c][jw] & bit) != 0u;
            m += sel ? v : v * SCL;
            cnt += sel ? 1 : 0;
        }
        msh[tid] = m;
        c0[tid]  = (unsigned char)cnt;
    }

    // ---- pass 1: mean + c+ + c-  (all independent of anchor) -------------
    {
        float p  = act ? m * (1.0f / NC) : 0.f;
        float ps = act ? m : 0.f;
        float cpv = (p > 0.f) ? p * p : 0.f;
        float cmv = (p < 0.f) ? p * p : 0.f;
        for (int o = 16; o; o >>= 1) {
            ps  += __shfl_xor_sync(0xFFFFFFFFu, ps,  o);
            cpv += __shfl_xor_sync(0xFFFFFFFFu, cpv, o);
            cmv += __shfl_xor_sync(0xFFFFFFFFu, cmv, o);
        }
        if (lane == 0) { redf[warp] = ps; redf2[warp] = cpv; redf3[warp] = cmv; }
        __syncthreads();
        if (warp == 0) {
            float a = redf[lane], c = redf2[lane], d = redf3[lane];
            for (int o = 16; o; o >>= 1) {
                a += __shfl_xor_sync(0xFFFFFFFFu, a, o);
                c += __shfl_xor_sync(0xFFFFFFFFu, c, o);
                d += __shfl_xor_sync(0xFFFFFFFFu, d, o);
            }
            if (lane == 0) { s_mean = a / (float)NS; s_cp = c; s_cm = d; }
        }
        __syncthreads();
    }

    // ---- pass 2: anchor = argmax(binary*m/C), first-index tie-break ------
    {
        float bv = -1e30f; int bi = NS;
        if (act) { float v = (m > s_mean) ? m * (1.0f / NC) : 0.0f; bv = v; bi = tid; }
        for (int o = 16; o; o >>= 1) {
            float ov = __shfl_xor_sync(0xFFFFFFFFu, bv, o);
            int   oi = __shfl_xor_sync(0xFFFFFFFFu, bi, o);
            if (ov > bv || (ov == bv && oi < bi)) { bv = ov; bi = oi; }
        }
        if (lane == 0) { redf[warp] = bv; redi[warp] = bi; }
        __syncthreads();
        if (warp == 0) {
            float v = redf[lane]; int i = redi[lane];
            for (int o = 16; o; o >>= 1) {
                float ov = __shfl_xor_sync(0xFFFFFFFFu, v, o);
                int   oi = __shfl_xor_sync(0xFFFFFFFFu, i, o);
                if (ov > v || (ov == v && oi < i)) { v = ov; i = oi; }
            }
            if (lane == 0) { s_anchor = i; s_pa = msh[i] * (1.0f / NC); }
        }
        __syncthreads();
    }
    const int anchor = s_anchor;
    const float ai = (float)(anchor / NH), aj = (float)(anchor % NH);

    // ---- pass 3: w0 = sum pw*dist, w1 = sum pw*ang -----------------------
    {
        float w0 = 0.f, w1s = 0.f;
        if (act) {
            float p   = m * (1.0f / NC);
            float rc0 = ((float)(tid / NH) - ai) / (float)NH;
            float rc1 = ((float)(tid % NH) - aj) / (float)NH;
            w0  = p * sqrtf(rc0 * rc0 + rc1 * rc1);
            w1s = p * (atan2f(rc1, rc0) * 0.3183098861837907f + 1.0f) * 0.5f;
        }
        for (int o = 16; o; o >>= 1) {
            w0  += __shfl_xor_sync(0xFFFFFFFFu, w0,  o);
            w1s += __shfl_xor_sync(0xFFFFFFFFu, w1s, o);
        }
        if (lane == 0) { redf[warp] = w0; redf4[warp] = w1s; }
        __syncthreads();
        if (warp == 0) {
            float a = redf[lane], bb = redf4[lane];
            for (int o = 16; o; o >>= 1) {
                a  += __shfl_xor_sync(0xFFFFFFFFu, a,  o);
                bb += __shfl_xor_sync(0xFFFFFFFFu, bb, o);
            }
            if (lane == 0) { s_w0 = a; s_w1 = bb; }
        }
        __syncthreads();
    }

    // ---- coef[k] = (u>0 ? cp : cm) * u  (cp*u+ - cm*u- collapses) --------
    if (tid < KHID) {
        float u = s_w0 * w1[tid] + s_w1 * w1[KHID + tid];
        scoef[tid] = u * (u > 0.f ? s_cp : s_cm);
    }

    // ---- 3x3 conv + per-warp value histogram -----------------------------
    int vcc = 0; unsigned mm;
    if (act) {
        int i0 = tid / NH, j0 = tid % NH;
        #pragma unroll
        for (int di = -1; di <= 1; di++)
            #pragma unroll
            for (int dj = -1; dj <= 1; dj++) {
                int ii = i0 + di, jj = j0 + dj;
                if (ii >= 0 && ii < NH && jj >= 0 && jj < NH)
                    vcc += (2 - abs(di)) * (2 - abs(dj)) * (int)c0[ii * NH + jj];
            }
    }
    {
        int key = act ? vcc : 999;
        mm = __match_any_sync(0xFFFFFFFFu, key);
        if (act && lane == (__ffs(mm) - 1))
            whist[warp][vcc] = (unsigned char)__popc(mm);
    }
    __syncthreads();

    // ---- sfx[v] = # strictly greater (suffix over 256 bins) --------------
    if (tid < 256) {
        int h = 0;
        #pragma unroll
        for (int r = 0; r < NWA; r++) h += (int)whist[r][tid];
        int s = h;
        #pragma unroll
        for (int o = 1; o < 32; o <<= 1) {
            int n = __shfl_up_sync(0xFFFFFFFFu, s, o);
            if (lane >= o) s += n;
        }
        if (lane == 31) redi[tid >> 5] = s;
        __syncthreads();
        int off = 0, total = 0;
        #pragma unroll
        for (int r = 0; r < 8; r++) {
            int w = redi[r]; total += w; if (r < (tid >> 5)) off += w;
        }
        sfx[tid] = total - (s + off);
    } else {
        __syncthreads();
    }
    __syncthreads();

    // ---- stable descending ranks -> smem patch list ----------------------
    if (act) {
        int g = sfx[vcc];
        if (g < seln) {
            int e = __popc(mm & ((1u << lane) - 1u));
            for (int r = 0; r < warp; r++) e += (int)whist[r][vcc];
            int rk = g + e;                 // ties by ascending index (stable)
            if (rk < seln) spatch[rk] = (short)(tid + 1);
        }
    }

    // ---- GEMV (float4): 192 col-groups (= full 768 cols) x 4 k-chunks ----
    // Both sub-blocks compute the FULL row-0 vector and write identical
    // values (deterministic duplicate write).
    if (tid < 768) {
        const int g  = tid % 192;           // 4 cols per group, covers all ND
        const int ks = tid / 192;           // 0..3, 128 k each
        const float4* w4 = (const float4*)w2 + g;
        float4 acc = make_float4(0.f, 0.f, 0.f, 0.f);
        #pragma unroll 8
        for (int k = ks * 128; k < ks * 128 + 128; k++) {
            float c = scoef[k];
            float4 w = __ldg(w4 + (size_t)k * (ND / 4));
            acc.x += c * w.x; acc.y += c * w.y; acc.z += c * w.z; acc.w += c * w.w;
        }
        gp4[tid] = acc;
    }
    __syncthreads();
    if (tid < 192) {
        float4 a = gp4[tid], b2 = gp4[192 + tid], c2 = gp4[384 + tid], d2 = gp4[576 + tid];
        float4 v;
        v.x = s_pa * (a.x + b2.x + c2.x + d2.x);
        v.y = s_pa * (a.y + b2.y + c2.y + d2.y);
        v.z = s_pa * (a.z + b2.z + c2.z + d2.z);
        v.w = s_pa * (a.w + b2.w + c2.w + d2.w);
        v.x = v.x > 0.f ? v.x : 0.2f * v.x;
        v.y = v.y > 0.f ? v.y : 0.2f * v.y;
        v.z = v.z > 0.f ? v.z : 0.2f * v.z;
        v.w = v.w > 0.f ? v.w : 0.2f * v.w;
        const int fi4 = b * NNtok * (ND / 4) + tid;        // row 0 of batch b
        float4 h4 = ((const float4*)hs)[fi4];
        v.x += h4.x; v.y += h4.y; v.z += h4.z; v.w += h4.w;
        ((float4*)out)[fi4] = v;
    }

    // ---- gather: this sub-block handles rows q = sub, sub+2, ... ---------
    {
        const float4* hin = (const float4*)hs;
        float4* o4 = (float4*)out;
        const int nh = (seln - sub + 1) / 2;               // # rows we own
        const int tot = nh * (ND / 4);
        for (int t = tid; t < tot; t += TPB) {
            int r  = t / (ND / 4);
            int d4 = t - r * (ND / 4);
            int q  = 2 * r + sub;
            int p  = (int)spatch[q];       // in [1,784]: unmodified hs rows
            __stcs(o4 + NB * NNtok * (ND / 4) + (b * seln + q) * (ND / 4) + d4,
                   __ldcs(hin + (b * NNtok + p) * (ND / 4) + d4));
        }
    }
}

// ---------------- launch ----------------
extern "C" void kernel_launch(void* const* d_in, const int* in_sizes, int n_in,
                              void* d_out, int out_size)
{
    const float* hs = (const float*)d_in[0];
    const float* x  = (const float*)d_in[1];
    const float* w1 = (const float*)d_in[2];
    const float* w2 = (const float*)d_in[3];

    const int hs_elems = NB * NNtok * ND;
    int seln = (out_size - hs_elems) / (NB * ND);
    if (seln < 1) seln = 1;
    if (seln > NS) seln = NS;

    kAll<<<NCB + NCPB, TPB>>>(x, w1, w2, hs, (float*)d_out, seln);
}